// round 5
// baseline (speedup 1.0000x reference)
#include <cuda_runtime.h>
#include <cuda_bf16.h>
#include <math_constants.h>
#include <float.h>

// VectorQuantizer: N=32768 rows, D=256, K=4096.
// bf16 tensor-core filter (certified margin) + exact fp32 rescore.
// Exact chain (verified rel_err=0.0 R1-R4):
//   dist = fl( fl(A_r + B_k) - fl(2 * dot_seq_fma(x_r,c_k)) ), argmin lowest
//   index on ties.
// R5: GEMM de-stalled — cp.async double-buffered c-tiles (1 sync/tile),
// epilogue uses private running min + stale shared atomicMin (no 2nd sync).
// Superset guarantee unchanged: threshold base is always an observed dist-hat.

#define VQ_N 32768
#define VQ_D 256
#define VQ_K 4096

#define GM  64    // rows per CTA in gemm
#define GN  64    // codewords per tile
#define NT  (VQ_K / GN)
#define CAP 256   // candidate capacity per row
#define XW  132   // smem pitch in 32-bit words (conflict-free: 132 % 32 == 4)

__device__ __nv_bfloat16 g_xh[VQ_N * VQ_D];
__device__ __nv_bfloat16 g_ch[VQ_K * VQ_D];
__device__ float    g_A[VQ_N];
__device__ float    g_S1[VQ_N];
__device__ float    g_B[VQ_K];
__device__ unsigned g_cmaxbits;
__device__ int      g_candCnt[VQ_N];
__device__ int      g_cand[VQ_N * CAP];
__device__ int      g_ind[VQ_N];
__device__ double   g_losssum;

// ---------------------------------------------------------------- cp.async helpers
__device__ __forceinline__ unsigned smem_u32(const void* p) {
    return (unsigned)__cvta_generic_to_shared(p);
}
__device__ __forceinline__ void cp16(unsigned dst, const void* src) {
    asm volatile("cp.async.cg.shared.global [%0], [%1], 16;\n" :: "r"(dst), "l"(src));
}
#define CP_COMMIT() asm volatile("cp.async.commit_group;\n")
#define CP_WAIT0()  asm volatile("cp.async.wait_group 0;\n")

// ---------------------------------------------------------------- zero
__global__ void vq_zero_kernel() {
    int i = blockIdx.x * blockDim.x + threadIdx.x;
    if (i < VQ_N) g_candCnt[i] = 0;
    if (i == 0) { g_losssum = 0.0; g_cmaxbits = 0u; }
}

// ---------------------------------------------------------------- prep x: bf16 copy + exact norms
__global__ __launch_bounds__(256) void vq_prep_x(const float* __restrict__ x) {
    __shared__ float sx[32][257];
    const int tid = threadIdx.x;
    const int row0 = blockIdx.x * 32;
#pragma unroll
    for (int it = 0; it < 8; it++) {
        int idx = tid + it * 256;
        int r   = idx >> 6;
        int c4  = idx & 63;
        float4 v = ((const float4*)(x + (size_t)(row0 + r) * VQ_D))[c4];
        sx[r][c4 * 4 + 0] = v.x; sx[r][c4 * 4 + 1] = v.y;
        sx[r][c4 * 4 + 2] = v.z; sx[r][c4 * 4 + 3] = v.w;
        __nv_bfloat162 p0, p1;
        p0.x = __float2bfloat16(v.x); p0.y = __float2bfloat16(v.y);
        p1.x = __float2bfloat16(v.z); p1.y = __float2bfloat16(v.w);
        __nv_bfloat162* dst = (__nv_bfloat162*)(g_xh + (size_t)(row0 + r) * VQ_D);
        dst[c4 * 2] = p0; dst[c4 * 2 + 1] = p1;
    }
    __syncthreads();
    if (tid < 32) {
        float s = 0.0f, s1 = 0.0f;
        for (int i = 0; i < VQ_D; i++) {
            float v = sx[tid][i];
            s  = __fadd_rn(s, __fmul_rn(v, v));   // strict sequential ascending
            s1 += fabsf(v);
        }
        g_A[row0 + tid]  = s;
        g_S1[row0 + tid] = s1;
    }
}

// ---------------------------------------------------------------- prep c
__global__ __launch_bounds__(256) void vq_prep_c(const float* __restrict__ cb) {
    __shared__ float sc[32][257];
    __shared__ float smax[256];
    const int tid = threadIdx.x;
    const int row0 = blockIdx.x * 32;
    float m = 0.0f;
#pragma unroll
    for (int it = 0; it < 8; it++) {
        int idx = tid + it * 256;
        int r   = idx >> 6;
        int c4  = idx & 63;
        float4 v = ((const float4*)(cb + (size_t)(row0 + r) * VQ_D))[c4];
        sc[r][c4 * 4 + 0] = v.x; sc[r][c4 * 4 + 1] = v.y;
        sc[r][c4 * 4 + 2] = v.z; sc[r][c4 * 4 + 3] = v.w;
        m = fmaxf(m, fmaxf(fmaxf(fabsf(v.x), fabsf(v.y)), fmaxf(fabsf(v.z), fabsf(v.w))));
        __nv_bfloat162 p0, p1;
        p0.x = __float2bfloat16(v.x); p0.y = __float2bfloat16(v.y);
        p1.x = __float2bfloat16(v.z); p1.y = __float2bfloat16(v.w);
        __nv_bfloat162* dst = (__nv_bfloat162*)(g_ch + (size_t)(row0 + r) * VQ_D);
        dst[c4 * 2] = p0; dst[c4 * 2 + 1] = p1;
    }
    smax[tid] = m;
    __syncthreads();
    if (tid < 32) {
        float s = 0.0f;
        for (int i = 0; i < VQ_D; i++) {
            float v = sc[tid][i];
            s = __fadd_rn(s, __fmul_rn(v, v));    // strict sequential ascending
        }
        g_B[row0 + tid] = s;
    }
    for (int s = 128; s > 0; s >>= 1) {
        if (tid < s) smax[tid] = fmaxf(smax[tid], smax[tid + s]);
        __syncthreads();
    }
    if (tid == 0) atomicMax(&g_cmaxbits, __float_as_uint(smax[0]));
}

// ---------------------------------------------------------------- bf16 MMA gemm + candidate collect
__device__ __forceinline__ void mma16816(float c[4], unsigned a0, unsigned a1,
                                         unsigned a2, unsigned a3,
                                         unsigned b0, unsigned b1) {
    asm volatile(
        "mma.sync.aligned.m16n8k16.row.col.f32.bf16.bf16.f32 "
        "{%0,%1,%2,%3}, {%4,%5,%6,%7}, {%8,%9}, {%0,%1,%2,%3};\n"
        : "+f"(c[0]), "+f"(c[1]), "+f"(c[2]), "+f"(c[3])
        : "r"(a0), "r"(a1), "r"(a2), "r"(a3), "r"(b0), "r"(b1));
}

__global__ __launch_bounds__(256, 2) void vq_gemm_kernel() {
    extern __shared__ unsigned smem_dyn[];
    unsigned* xsw = smem_dyn;                    // GM x XW
    unsigned* csw = smem_dyn + GM * XW;          // 2 x (GN x XW)
    __shared__ unsigned s_rowmin[GM];

    const int tid  = threadIdx.x;
    const int w    = tid >> 5;
    const int lane = tid & 31;
    const int g    = lane >> 2;
    const int tg   = lane & 3;
    const int rowbase = (w >> 1) * 16;    // 4 row-groups of 16
    const int colbase = (w & 1) * 32;     // 2 col-groups of 32
    const int row0 = blockIdx.x * GM;

    // async-load x tile [GM x 256 bf16] and c tile 0
#pragma unroll
    for (int it = 0; it < 2; it++) {
        int idx = tid + it * 256;         // 0..511
        int r   = idx >> 3;               // 0..63
        int s   = idx & 7;                // uint4 slot base (x4)
#pragma unroll
        for (int q = 0; q < 4; q++) {
            int sl = s * 4 + q;           // 0..31
            cp16(smem_u32(xsw + r * XW + sl * 4),
                 (const uint4*)(g_xh + (size_t)(row0 + r) * VQ_D) + sl);
            cp16(smem_u32(csw + r * XW + sl * 4),
                 (const uint4*)(g_ch + (size_t)r * VQ_D) + sl);
        }
    }
    CP_COMMIT();
    if (tid < GM) s_rowmin[tid] = 0x7f7fffffu;   // FLT_MAX bits

    // per-thread rows: g and g+8 within row-group
    int   lrow[2];
    float Arow[2], thr[2], runmin[2];
    float cmax = __uint_as_float(g_cmaxbits);
#pragma unroll
    for (int mi = 0; mi < 2; mi++) {
        int lr = rowbase + mi * 8 + g;
        lrow[mi]   = lr;
        Arow[mi]   = g_A[row0 + lr];
        thr[mi]    = 0.033f * cmax * g_S1[row0 + lr] + 4.0e-4f;  // certified 2*eps, padded
        runmin[mi] = FLT_MAX;
    }

    CP_WAIT0();
    __syncthreads();

    for (int t = 0; t < NT; t++) {
        unsigned* cur = csw + (t & 1) * (GN * XW);
        if (t + 1 < NT) {
            unsigned* nxt = csw + ((t + 1) & 1) * (GN * XW);
            const __nv_bfloat16* src = g_ch + (size_t)(t + 1) * GN * VQ_D;
            int r = tid >> 2;                  // 0..63
            int s = (tid & 3) * 8;             // uint4 slots s..s+7
#pragma unroll
            for (int q = 0; q < 8; q++) {
                int sl = s + q;
                cp16(smem_u32(nxt + r * XW + sl * 4),
                     (const uint4*)(src + (size_t)r * VQ_D) + sl);
            }
            CP_COMMIT();
        }

        float acc[4][4];
#pragma unroll
        for (int nt = 0; nt < 4; nt++)
#pragma unroll
            for (int q = 0; q < 4; q++) acc[nt][q] = 0.0f;

#pragma unroll
        for (int i = 0; i < 16; i++) {
            int dw = i * 8;
            const unsigned* p  = xsw + (rowbase + g) * XW + dw + tg;
            unsigned a0 = p[0], a1 = p[8 * XW], a2 = p[4], a3 = p[8 * XW + 4];
#pragma unroll
            for (int nt = 0; nt < 4; nt++) {
                const unsigned* pb = cur + (colbase + nt * 8 + g) * XW + dw + tg;
                mma16816(acc[nt], a0, a1, a2, a3, pb[0], pb[4]);
            }
        }

        // epilogue: dist, local min, threshold vs (stale shared min | running min)
        const int kb = t * GN + colbase;
        float lmin[2] = {FLT_MAX, FLT_MAX};
#pragma unroll
        for (int nt = 0; nt < 4; nt++) {
            float B0 = g_B[kb + nt * 8 + 2 * tg];
            float B1 = g_B[kb + nt * 8 + 2 * tg + 1];
            float d00 = (Arow[0] + B0) - 2.0f * acc[nt][0];
            float d01 = (Arow[0] + B1) - 2.0f * acc[nt][1];
            float d10 = (Arow[1] + B0) - 2.0f * acc[nt][2];
            float d11 = (Arow[1] + B1) - 2.0f * acc[nt][3];
            acc[nt][0] = d00; acc[nt][1] = d01;
            acc[nt][2] = d10; acc[nt][3] = d11;
            lmin[0] = fminf(lmin[0], fminf(d00, d01));
            lmin[1] = fminf(lmin[1], fminf(d10, d11));
        }
        float rm[2];
#pragma unroll
        for (int mi = 0; mi < 2; mi++) {
            runmin[mi] = fminf(runmin[mi], lmin[mi]);
            float shared_min = __uint_as_float(s_rowmin[lrow[mi]]);  // stale: prev tiles
            rm[mi] = fminf(shared_min, runmin[mi]) + thr[mi];
            atomicMin(&s_rowmin[lrow[mi]], __float_as_uint(lmin[mi]));
        }
#pragma unroll
        for (int nt = 0; nt < 4; nt++) {
            int kA = kb + nt * 8 + 2 * tg;
#pragma unroll
            for (int q = 0; q < 4; q++) {
                int mi = q >> 1;
                if (acc[nt][q] < rm[mi]) {
                    int grow = row0 + lrow[mi];
                    int pos = atomicAdd(&g_candCnt[grow], 1);
                    if (pos < CAP) g_cand[grow * CAP + pos] = kA + (q & 1);
                }
            }
        }

        CP_WAIT0();
        __syncthreads();   // next tile's buffer ready; all reads of cur done
    }
}

// ---------------------------------------------------------------- exact rescore (warp per row)
__device__ __forceinline__ float exact_dist(const float* __restrict__ xr,
                                            const float* __restrict__ ck,
                                            float Ar, float Bk) {
    float acc = 0.0f;
    const float4* x4 = (const float4*)xr;
    const float4* c4 = (const float4*)ck;
#pragma unroll 4
    for (int i = 0; i < VQ_D / 4; i++) {
        float4 a = __ldg(x4 + i);
        float4 b = __ldg(c4 + i);
        acc = __fmaf_rn(a.x, b.x, acc);
        acc = __fmaf_rn(a.y, b.y, acc);
        acc = __fmaf_rn(a.z, b.z, acc);
        acc = __fmaf_rn(a.w, b.w, acc);
    }
    float t  = __fadd_rn(Ar, Bk);
    float m2 = __fmul_rn(2.0f, acc);
    return __fsub_rn(t, m2);
}

__global__ void vq_rescore_kernel(const float* __restrict__ x,
                                  const float* __restrict__ cb) {
    int row  = blockIdx.x * 8 + (threadIdx.x >> 5);
    int lane = threadIdx.x & 31;
    if (row >= VQ_N) return;
    int cnt = g_candCnt[row];
    const float* xr = x + (size_t)row * VQ_D;
    float Ar = g_A[row];

    float best = FLT_MAX;
    int   besti = 0x7fffffff;
    if (cnt <= CAP) {
        for (int j = lane; j < cnt; j += 32) {
            int k = g_cand[row * CAP + j];
            float d = exact_dist(xr, cb + (size_t)k * VQ_D, Ar, g_B[k]);
            if (d < best || (d == best && k < besti)) { best = d; besti = k; }
        }
    } else {
        for (int k = lane; k < VQ_K; k += 32) {
            float d = exact_dist(xr, cb + (size_t)k * VQ_D, Ar, g_B[k]);
            if (d < best || (d == best && k < besti)) { best = d; besti = k; }
        }
    }
#pragma unroll
    for (int off = 16; off > 0; off >>= 1) {
        float v = __shfl_down_sync(0xffffffffu, best, off);
        int   i = __shfl_down_sync(0xffffffffu, besti, off);
        if (v < best || (v == best && i < besti)) { best = v; besti = i; }
    }
    if (lane == 0) g_ind[row] = besti;
}

// ---------------------------------------------------------------- output + loss accum
__global__ void vq_output_kernel(const float* __restrict__ x,
                                 const float* __restrict__ cb,
                                 float* __restrict__ out)
{
    __shared__ double sd[256];
    int e4 = blockIdx.x * blockDim.x + threadIdx.x;
    double ls = 0.0;
    if (e4 < VQ_N * VQ_D / 4) {
        int base = e4 * 4;
        int row  = base >> 8;
        int col  = base & 255;
        int ind  = g_ind[row];
        float4 xv = *(const float4*)(x  + base);
        float4 qv = *(const float4*)(cb + (size_t)ind * VQ_D + col);
        float d0 = __fsub_rn(qv.x, xv.x);
        float d1 = __fsub_rn(qv.y, xv.y);
        float d2 = __fsub_rn(qv.z, xv.z);
        float d3 = __fsub_rn(qv.w, xv.w);
        float4 ov;
        ov.x = __fadd_rn(xv.x, d0);
        ov.y = __fadd_rn(xv.y, d1);
        ov.z = __fadd_rn(xv.z, d2);
        ov.w = __fadd_rn(xv.w, d3);
        *(float4*)(out + base) = ov;
        ls = (double)__fmul_rn(d0, d0) + (double)__fmul_rn(d1, d1)
           + (double)__fmul_rn(d2, d2) + (double)__fmul_rn(d3, d3);
    }
    sd[threadIdx.x] = ls;
    __syncthreads();
    for (int s = 128; s > 0; s >>= 1) {
        if (threadIdx.x < s) sd[threadIdx.x] += sd[threadIdx.x + s];
        __syncthreads();
    }
    if (threadIdx.x == 0) atomicAdd(&g_losssum, sd[0]);
}

// ---------------------------------------------------------------- finalize loss
__global__ void vq_finalize_kernel(float* __restrict__ out, int has_loss) {
    if (!has_loss) return;
    float m = (float)(g_losssum * (1.0 / (double)(VQ_N * VQ_D)));
    float commit = __fmul_rn(m, 0.25f);
    out[VQ_N * VQ_D] = __fadd_rn(commit, m);
}

// ---------------------------------------------------------------- launch
extern "C" void kernel_launch(void* const* d_in, const int* in_sizes, int n_in,
                              void* d_out, int out_size)
{
    const float* latents  = (const float*)d_in[0];
    const float* codebook = (const float*)d_in[1];
    if (n_in >= 2 && in_sizes[0] == VQ_K * VQ_D && in_sizes[1] == VQ_N * VQ_D) {
        latents  = (const float*)d_in[1];
        codebook = (const float*)d_in[0];
    }
    float* out = (float*)d_out;
    int has_loss = (out_size > VQ_N * VQ_D) ? 1 : 0;

    const int GEMM_SMEM = (GM * XW + 2 * GN * XW) * 4;   // 101376 bytes
    cudaFuncSetAttribute(vq_gemm_kernel,
                         cudaFuncAttributeMaxDynamicSharedMemorySize, GEMM_SMEM);

    vq_zero_kernel<<<VQ_N / 256, 256>>>();
    vq_prep_c<<<VQ_K / 32, 256>>>(codebook);
    vq_prep_x<<<VQ_N / 32, 256>>>(latents);
    vq_gemm_kernel<<<VQ_N / GM, 256, GEMM_SMEM>>>();
    vq_rescore_kernel<<<VQ_N / 8, 256>>>(latents, codebook);
    vq_output_kernel<<<(VQ_N * VQ_D / 4) / 256, 256>>>(latents, codebook, out);
    vq_finalize_kernel<<<1, 1>>>(out, has_loss);
}

// round 6
// speedup vs baseline: 1.4238x; 1.4238x over previous
#include <cuda_runtime.h>
#include <cuda_bf16.h>
#include <math_constants.h>
#include <float.h>

// VectorQuantizer: N=32768 rows, D=256, K=4096.
// bf16 tensor-core filter (certified margin) + exact fp32 rescore.
// Exact chain (verified rel_err=0.0 R1-R5):
//   dist = fl( fl(A_r + B_k) - fl(2 * dot_seq_fma(x_r,c_k)) ), argmin lowest
//   index on ties.
// R6: GM=256 / 512 threads -> grid=128 = ONE wave; cp.async double-buffered
// GN=64 c-tiles (1 sync/tile); quad-reduced shared atomics in epilogue.

#define VQ_N 32768
#define VQ_D 256
#define VQ_K 4096

#define GM  256   // rows per CTA in gemm
#define GN  64    // codewords per tile
#define NT  (VQ_K / GN)
#define CAP 256   // candidate capacity per row
#define XW  132   // smem pitch in 32-bit words
#define GT  512   // gemm threads

__device__ __nv_bfloat16 g_xh[VQ_N * VQ_D];
__device__ __nv_bfloat16 g_ch[VQ_K * VQ_D];
__device__ float    g_A[VQ_N];
__device__ float    g_S1[VQ_N];
__device__ float    g_B[VQ_K];
__device__ unsigned g_cmaxbits;
__device__ int      g_candCnt[VQ_N];
__device__ int      g_cand[VQ_N * CAP];
__device__ int      g_ind[VQ_N];
__device__ double   g_losssum;

// ---------------------------------------------------------------- cp.async helpers
__device__ __forceinline__ unsigned smem_u32(const void* p) {
    return (unsigned)__cvta_generic_to_shared(p);
}
__device__ __forceinline__ void cp16(unsigned dst, const void* src) {
    asm volatile("cp.async.cg.shared.global [%0], [%1], 16;\n" :: "r"(dst), "l"(src));
}
#define CP_COMMIT() asm volatile("cp.async.commit_group;\n")
#define CP_WAIT0()  asm volatile("cp.async.wait_group 0;\n")

// ---------------------------------------------------------------- zero
__global__ void vq_zero_kernel() {
    int i = blockIdx.x * blockDim.x + threadIdx.x;
    if (i < VQ_N) g_candCnt[i] = 0;
    if (i == 0) { g_losssum = 0.0; g_cmaxbits = 0u; }
}

// ---------------------------------------------------------------- prep x: bf16 copy + exact norms
__global__ __launch_bounds__(256) void vq_prep_x(const float* __restrict__ x) {
    __shared__ float sx[32][257];
    const int tid = threadIdx.x;
    const int row0 = blockIdx.x * 32;
#pragma unroll
    for (int it = 0; it < 8; it++) {
        int idx = tid + it * 256;
        int r   = idx >> 6;
        int c4  = idx & 63;
        float4 v = ((const float4*)(x + (size_t)(row0 + r) * VQ_D))[c4];
        sx[r][c4 * 4 + 0] = v.x; sx[r][c4 * 4 + 1] = v.y;
        sx[r][c4 * 4 + 2] = v.z; sx[r][c4 * 4 + 3] = v.w;
        __nv_bfloat162 p0, p1;
        p0.x = __float2bfloat16(v.x); p0.y = __float2bfloat16(v.y);
        p1.x = __float2bfloat16(v.z); p1.y = __float2bfloat16(v.w);
        __nv_bfloat162* dst = (__nv_bfloat162*)(g_xh + (size_t)(row0 + r) * VQ_D);
        dst[c4 * 2] = p0; dst[c4 * 2 + 1] = p1;
    }
    __syncthreads();
    if (tid < 32) {
        float s = 0.0f, s1 = 0.0f;
        for (int i = 0; i < VQ_D; i++) {
            float v = sx[tid][i];
            s  = __fadd_rn(s, __fmul_rn(v, v));   // strict sequential ascending
            s1 += fabsf(v);
        }
        g_A[row0 + tid]  = s;
        g_S1[row0 + tid] = s1;
    }
}

// ---------------------------------------------------------------- prep c
__global__ __launch_bounds__(256) void vq_prep_c(const float* __restrict__ cb) {
    __shared__ float sc[32][257];
    __shared__ float smax[256];
    const int tid = threadIdx.x;
    const int row0 = blockIdx.x * 32;
    float m = 0.0f;
#pragma unroll
    for (int it = 0; it < 8; it++) {
        int idx = tid + it * 256;
        int r   = idx >> 6;
        int c4  = idx & 63;
        float4 v = ((const float4*)(cb + (size_t)(row0 + r) * VQ_D))[c4];
        sc[r][c4 * 4 + 0] = v.x; sc[r][c4 * 4 + 1] = v.y;
        sc[r][c4 * 4 + 2] = v.z; sc[r][c4 * 4 + 3] = v.w;
        m = fmaxf(m, fmaxf(fmaxf(fabsf(v.x), fabsf(v.y)), fmaxf(fabsf(v.z), fabsf(v.w))));
        __nv_bfloat162 p0, p1;
        p0.x = __float2bfloat16(v.x); p0.y = __float2bfloat16(v.y);
        p1.x = __float2bfloat16(v.z); p1.y = __float2bfloat16(v.w);
        __nv_bfloat162* dst = (__nv_bfloat162*)(g_ch + (size_t)(row0 + r) * VQ_D);
        dst[c4 * 2] = p0; dst[c4 * 2 + 1] = p1;
    }
    smax[tid] = m;
    __syncthreads();
    if (tid < 32) {
        float s = 0.0f;
        for (int i = 0; i < VQ_D; i++) {
            float v = sc[tid][i];
            s = __fadd_rn(s, __fmul_rn(v, v));    // strict sequential ascending
        }
        g_B[row0 + tid] = s;
    }
    for (int s = 128; s > 0; s >>= 1) {
        if (tid < s) smax[tid] = fmaxf(smax[tid], smax[tid + s]);
        __syncthreads();
    }
    if (tid == 0) atomicMax(&g_cmaxbits, __float_as_uint(smax[0]));
}

// ---------------------------------------------------------------- bf16 MMA gemm + candidate collect
__device__ __forceinline__ void mma16816(float c[4], unsigned a0, unsigned a1,
                                         unsigned a2, unsigned a3,
                                         unsigned b0, unsigned b1) {
    asm volatile(
        "mma.sync.aligned.m16n8k16.row.col.f32.bf16.bf16.f32 "
        "{%0,%1,%2,%3}, {%4,%5,%6,%7}, {%8,%9}, {%0,%1,%2,%3};\n"
        : "+f"(c[0]), "+f"(c[1]), "+f"(c[2]), "+f"(c[3])
        : "r"(a0), "r"(a1), "r"(a2), "r"(a3), "r"(b0), "r"(b1));
}

__global__ __launch_bounds__(GT, 1) void vq_gemm_kernel() {
    extern __shared__ unsigned smem_dyn[];
    unsigned* xsw = smem_dyn;                    // GM x XW
    unsigned* csw = smem_dyn + GM * XW;          // 2 x (GN x XW)
    __shared__ unsigned s_rowmin[GM];

    const int tid  = threadIdx.x;
    const int w    = tid >> 5;                   // 0..15
    const int lane = tid & 31;
    const int g    = lane >> 2;
    const int tg   = lane & 3;
    const int rowbase = (w >> 1) * 32;           // 8 row-groups of 32
    const int colbase = (w & 1) * 32;            // 2 col-groups of 32
    const int row0 = blockIdx.x * GM;

    // async-load x tile [GM x 256 bf16] and c tile 0
    for (int idx = tid; idx < GM * 32; idx += GT) {
        int r = idx >> 5, sl = idx & 31;
        cp16(smem_u32(xsw + r * XW + sl * 4),
             (const uint4*)(g_xh + (size_t)(row0 + r) * VQ_D) + sl);
    }
    for (int idx = tid; idx < GN * 32; idx += GT) {
        int r = idx >> 5, sl = idx & 31;
        cp16(smem_u32(csw + r * XW + sl * 4),
             (const uint4*)(g_ch + (size_t)r * VQ_D) + sl);
    }
    CP_COMMIT();
    if (tid < GM) s_rowmin[tid] = 0x7f7fffffu;   // FLT_MAX bits

    // per-thread rows: rowbase + (mi>>1)*16 + (mi&1)*8 + g
    int   lrow[4];
    float Arow[4], thr[4], runmin[4];
    float cmax = __uint_as_float(g_cmaxbits);
#pragma unroll
    for (int mi = 0; mi < 4; mi++) {
        int lr = rowbase + (mi >> 1) * 16 + (mi & 1) * 8 + g;
        lrow[mi]   = lr;
        Arow[mi]   = g_A[row0 + lr];
        thr[mi]    = 0.033f * cmax * g_S1[row0 + lr] + 4.0e-4f;  // certified 2*eps
        runmin[mi] = FLT_MAX;
    }

    CP_WAIT0();
    __syncthreads();

    for (int t = 0; t < NT; t++) {
        unsigned* cur = csw + (t & 1) * (GN * XW);
        if (t + 1 < NT) {
            unsigned* nxt = csw + ((t + 1) & 1) * (GN * XW);
            const __nv_bfloat16* src = g_ch + (size_t)(t + 1) * GN * VQ_D;
            for (int idx = tid; idx < GN * 32; idx += GT) {
                int r = idx >> 5, sl = idx & 31;
                cp16(smem_u32(nxt + r * XW + sl * 4),
                     (const uint4*)(src + (size_t)r * VQ_D) + sl);
            }
            CP_COMMIT();
        }

        float acc[2][4][4];
#pragma unroll
        for (int mt = 0; mt < 2; mt++)
#pragma unroll
            for (int nt = 0; nt < 4; nt++)
#pragma unroll
                for (int q = 0; q < 4; q++) acc[mt][nt][q] = 0.0f;

#pragma unroll
        for (int i = 0; i < 16; i++) {
            int dw = i * 8;
            unsigned a[2][4];
#pragma unroll
            for (int mt = 0; mt < 2; mt++) {
                const unsigned* p  = xsw + (rowbase + mt * 16 + g) * XW + dw + tg;
                const unsigned* p8 = p + 8 * XW;
                a[mt][0] = p[0];  a[mt][2] = p[4];
                a[mt][1] = p8[0]; a[mt][3] = p8[4];
            }
#pragma unroll
            for (int nt = 0; nt < 4; nt++) {
                const unsigned* pb = cur + (colbase + nt * 8 + g) * XW + dw + tg;
                unsigned b0 = pb[0], b1 = pb[4];
                mma16816(acc[0][nt], a[0][0], a[0][1], a[0][2], a[0][3], b0, b1);
                mma16816(acc[1][nt], a[1][0], a[1][1], a[1][2], a[1][3], b0, b1);
            }
        }

        // epilogue: dist, quad-reduced local min, stale-shared-min threshold
        const int kb = t * GN + colbase;
        float lmin[4] = {FLT_MAX, FLT_MAX, FLT_MAX, FLT_MAX};
#pragma unroll
        for (int nt = 0; nt < 4; nt++) {
            float B0 = g_B[kb + nt * 8 + 2 * tg];
            float B1 = g_B[kb + nt * 8 + 2 * tg + 1];
#pragma unroll
            for (int mt = 0; mt < 2; mt++) {
                float d00 = (Arow[2 * mt] + B0)     - 2.0f * acc[mt][nt][0];
                float d01 = (Arow[2 * mt] + B1)     - 2.0f * acc[mt][nt][1];
                float d10 = (Arow[2 * mt + 1] + B0) - 2.0f * acc[mt][nt][2];
                float d11 = (Arow[2 * mt + 1] + B1) - 2.0f * acc[mt][nt][3];
                acc[mt][nt][0] = d00; acc[mt][nt][1] = d01;
                acc[mt][nt][2] = d10; acc[mt][nt][3] = d11;
                lmin[2 * mt]     = fminf(lmin[2 * mt],     fminf(d00, d01));
                lmin[2 * mt + 1] = fminf(lmin[2 * mt + 1], fminf(d10, d11));
            }
        }
        // butterfly across the 4 tg lanes (same rows) -> quad min in all lanes
#pragma unroll
        for (int mi = 0; mi < 4; mi++) {
            lmin[mi] = fminf(lmin[mi], __shfl_xor_sync(0xffffffffu, lmin[mi], 1));
            lmin[mi] = fminf(lmin[mi], __shfl_xor_sync(0xffffffffu, lmin[mi], 2));
        }
        float rm[4];
#pragma unroll
        for (int mi = 0; mi < 4; mi++) {
            runmin[mi] = fminf(runmin[mi], lmin[mi]);
            float shared_min = __uint_as_float(s_rowmin[lrow[mi]]);  // stale: prev tiles
            rm[mi] = fminf(shared_min, runmin[mi]) + thr[mi];
            if (tg == 0)
                atomicMin(&s_rowmin[lrow[mi]], __float_as_uint(runmin[mi]));
        }
#pragma unroll
        for (int nt = 0; nt < 4; nt++) {
            int kA = kb + nt * 8 + 2 * tg;
#pragma unroll
            for (int mt = 0; mt < 2; mt++) {
#pragma unroll
                for (int q = 0; q < 4; q++) {
                    int mi = 2 * mt + (q >> 1);
                    if (acc[mt][nt][q] < rm[mi]) {
                        int grow = row0 + lrow[mi];
                        int pos = atomicAdd(&g_candCnt[grow], 1);
                        if (pos < CAP) g_cand[grow * CAP + pos] = kA + (q & 1);
                    }
                }
            }
        }

        CP_WAIT0();
        __syncthreads();   // next buffer ready; all reads of cur done
    }
}

// ---------------------------------------------------------------- exact rescore (warp per row)
__device__ __forceinline__ float exact_dist(const float* __restrict__ xr,
                                            const float* __restrict__ ck,
                                            float Ar, float Bk) {
    float acc = 0.0f;
    const float4* x4 = (const float4*)xr;
    const float4* c4 = (const float4*)ck;
#pragma unroll 4
    for (int i = 0; i < VQ_D / 4; i++) {
        float4 a = __ldg(x4 + i);
        float4 b = __ldg(c4 + i);
        acc = __fmaf_rn(a.x, b.x, acc);
        acc = __fmaf_rn(a.y, b.y, acc);
        acc = __fmaf_rn(a.z, b.z, acc);
        acc = __fmaf_rn(a.w, b.w, acc);
    }
    float t  = __fadd_rn(Ar, Bk);
    float m2 = __fmul_rn(2.0f, acc);
    return __fsub_rn(t, m2);
}

__global__ void vq_rescore_kernel(const float* __restrict__ x,
                                  const float* __restrict__ cb) {
    int row  = blockIdx.x * 8 + (threadIdx.x >> 5);
    int lane = threadIdx.x & 31;
    if (row >= VQ_N) return;
    int cnt = g_candCnt[row];
    const float* xr = x + (size_t)row * VQ_D;
    float Ar = g_A[row];

    float best = FLT_MAX;
    int   besti = 0x7fffffff;
    if (cnt <= CAP) {
        for (int j = lane; j < cnt; j += 32) {
            int k = g_cand[row * CAP + j];
            float d = exact_dist(xr, cb + (size_t)k * VQ_D, Ar, g_B[k]);
            if (d < best || (d == best && k < besti)) { best = d; besti = k; }
        }
    } else {
        for (int k = lane; k < VQ_K; k += 32) {
            float d = exact_dist(xr, cb + (size_t)k * VQ_D, Ar, g_B[k]);
            if (d < best || (d == best && k < besti)) { best = d; besti = k; }
        }
    }
#pragma unroll
    for (int off = 16; off > 0; off >>= 1) {
        float v = __shfl_down_sync(0xffffffffu, best, off);
        int   i = __shfl_down_sync(0xffffffffu, besti, off);
        if (v < best || (v == best && i < besti)) { best = v; besti = i; }
    }
    if (lane == 0) g_ind[row] = besti;
}

// ---------------------------------------------------------------- output + loss accum
__global__ void vq_output_kernel(const float* __restrict__ x,
                                 const float* __restrict__ cb,
                                 float* __restrict__ out)
{
    __shared__ double sd[256];
    int e4 = blockIdx.x * blockDim.x + threadIdx.x;
    double ls = 0.0;
    if (e4 < VQ_N * VQ_D / 4) {
        int base = e4 * 4;
        int row  = base >> 8;
        int col  = base & 255;
        int ind  = g_ind[row];
        float4 xv = *(const float4*)(x  + base);
        float4 qv = *(const float4*)(cb + (size_t)ind * VQ_D + col);
        float d0 = __fsub_rn(qv.x, xv.x);
        float d1 = __fsub_rn(qv.y, xv.y);
        float d2 = __fsub_rn(qv.z, xv.z);
        float d3 = __fsub_rn(qv.w, xv.w);
        float4 ov;
        ov.x = __fadd_rn(xv.x, d0);
        ov.y = __fadd_rn(xv.y, d1);
        ov.z = __fadd_rn(xv.z, d2);
        ov.w = __fadd_rn(xv.w, d3);
        *(float4*)(out + base) = ov;
        ls = (double)__fmul_rn(d0, d0) + (double)__fmul_rn(d1, d1)
           + (double)__fmul_rn(d2, d2) + (double)__fmul_rn(d3, d3);
    }
    sd[threadIdx.x] = ls;
    __syncthreads();
    for (int s = 128; s > 0; s >>= 1) {
        if (threadIdx.x < s) sd[threadIdx.x] += sd[threadIdx.x + s];
        __syncthreads();
    }
    if (threadIdx.x == 0) atomicAdd(&g_losssum, sd[0]);
}

// ---------------------------------------------------------------- finalize loss
__global__ void vq_finalize_kernel(float* __restrict__ out, int has_loss) {
    if (!has_loss) return;
    float m = (float)(g_losssum * (1.0 / (double)(VQ_N * VQ_D)));
    float commit = __fmul_rn(m, 0.25f);
    out[VQ_N * VQ_D] = __fadd_rn(commit, m);
}

// ---------------------------------------------------------------- launch
extern "C" void kernel_launch(void* const* d_in, const int* in_sizes, int n_in,
                              void* d_out, int out_size)
{
    const float* latents  = (const float*)d_in[0];
    const float* codebook = (const float*)d_in[1];
    if (n_in >= 2 && in_sizes[0] == VQ_K * VQ_D && in_sizes[1] == VQ_N * VQ_D) {
        latents  = (const float*)d_in[1];
        codebook = (const float*)d_in[0];
    }
    float* out = (float*)d_out;
    int has_loss = (out_size > VQ_N * VQ_D) ? 1 : 0;

    const int GEMM_SMEM = (GM * XW + 2 * GN * XW) * 4;   // 202752 bytes
    cudaFuncSetAttribute(vq_gemm_kernel,
                         cudaFuncAttributeMaxDynamicSharedMemorySize, GEMM_SMEM);

    vq_zero_kernel<<<VQ_N / 256, 256>>>();
    vq_prep_c<<<VQ_K / 32, 256>>>(codebook);
    vq_prep_x<<<VQ_N / 32, 256>>>(latents);
    vq_gemm_kernel<<<VQ_N / GM, GT, GEMM_SMEM>>>();
    vq_rescore_kernel<<<VQ_N / 8, 256>>>(latents, codebook);
    vq_output_kernel<<<(VQ_N * VQ_D / 4) / 256, 256>>>(latents, codebook, out);
    vq_finalize_kernel<<<1, 1>>>(out, has_loss);
}

// round 7
// speedup vs baseline: 1.4770x; 1.0374x over previous
#include <cuda_runtime.h>
#include <cuda_bf16.h>
#include <math_constants.h>
#include <float.h>

// VectorQuantizer: N=32768 rows, D=256, K=4096.
// bf16 tensor-core filter (certified margin) + exact fp32 rescore.
// Exact chain (verified rel_err=0.0 R1-R6):
//   dist = fl( fl(A_r + B_k) - fl(2 * dot_seq_fma(x_r,c_k)) ), argmin lowest
//   index on ties.
// R7: inner loop via ldmatrix.x4 (4 LDSM + 8 MMA per i-step instead of 16
// scalar LDS + 8 MMA) — attacks the issue/latency bound seen in R6
// (issue 27%, tensor 26%).

#define VQ_N 32768
#define VQ_D 256
#define VQ_K 4096

#define GM  256   // rows per CTA in gemm
#define GN  64    // codewords per tile
#define NT  (VQ_K / GN)
#define CAP 256   // candidate capacity per row
#define XW  132   // smem pitch in 32-bit words (4-bank row stride: conflict-free LDSM)
#define GT  512   // gemm threads

__device__ __nv_bfloat16 g_xh[VQ_N * VQ_D];
__device__ __nv_bfloat16 g_ch[VQ_K * VQ_D];
__device__ float    g_A[VQ_N];
__device__ float    g_S1[VQ_N];
__device__ float    g_B[VQ_K];
__device__ unsigned g_cmaxbits;
__device__ int      g_candCnt[VQ_N];
__device__ int      g_cand[VQ_N * CAP];
__device__ int      g_ind[VQ_N];
__device__ double   g_losssum;

// ---------------------------------------------------------------- helpers
__device__ __forceinline__ unsigned smem_u32(const void* p) {
    return (unsigned)__cvta_generic_to_shared(p);
}
__device__ __forceinline__ void cp16(unsigned dst, const void* src) {
    asm volatile("cp.async.cg.shared.global [%0], [%1], 16;\n" :: "r"(dst), "l"(src));
}
#define CP_COMMIT() asm volatile("cp.async.commit_group;\n")
#define CP_WAIT0()  asm volatile("cp.async.wait_group 0;\n")

__device__ __forceinline__ void ldsm4(unsigned& r0, unsigned& r1,
                                      unsigned& r2, unsigned& r3, unsigned addr) {
    asm volatile("ldmatrix.sync.aligned.m8n8.x4.shared.b16 {%0,%1,%2,%3}, [%4];\n"
                 : "=r"(r0), "=r"(r1), "=r"(r2), "=r"(r3) : "r"(addr));
}

__device__ __forceinline__ void mma16816(float c[4], unsigned a0, unsigned a1,
                                         unsigned a2, unsigned a3,
                                         unsigned b0, unsigned b1) {
    asm volatile(
        "mma.sync.aligned.m16n8k16.row.col.f32.bf16.bf16.f32 "
        "{%0,%1,%2,%3}, {%4,%5,%6,%7}, {%8,%9}, {%0,%1,%2,%3};\n"
        : "+f"(c[0]), "+f"(c[1]), "+f"(c[2]), "+f"(c[3])
        : "r"(a0), "r"(a1), "r"(a2), "r"(a3), "r"(b0), "r"(b1));
}

// ---------------------------------------------------------------- zero
__global__ void vq_zero_kernel() {
    int i = blockIdx.x * blockDim.x + threadIdx.x;
    if (i < VQ_N) g_candCnt[i] = 0;
    if (i == 0) { g_losssum = 0.0; g_cmaxbits = 0u; }
}

// ---------------------------------------------------------------- prep x: bf16 copy + exact norms
__global__ __launch_bounds__(256) void vq_prep_x(const float* __restrict__ x) {
    __shared__ float sx[32][257];
    const int tid = threadIdx.x;
    const int row0 = blockIdx.x * 32;
#pragma unroll
    for (int it = 0; it < 8; it++) {
        int idx = tid + it * 256;
        int r   = idx >> 6;
        int c4  = idx & 63;
        float4 v = ((const float4*)(x + (size_t)(row0 + r) * VQ_D))[c4];
        sx[r][c4 * 4 + 0] = v.x; sx[r][c4 * 4 + 1] = v.y;
        sx[r][c4 * 4 + 2] = v.z; sx[r][c4 * 4 + 3] = v.w;
        __nv_bfloat162 p0, p1;
        p0.x = __float2bfloat16(v.x); p0.y = __float2bfloat16(v.y);
        p1.x = __float2bfloat16(v.z); p1.y = __float2bfloat16(v.w);
        __nv_bfloat162* dst = (__nv_bfloat162*)(g_xh + (size_t)(row0 + r) * VQ_D);
        dst[c4 * 2] = p0; dst[c4 * 2 + 1] = p1;
    }
    __syncthreads();
    if (tid < 32) {
        float s = 0.0f, s1 = 0.0f;
        for (int i = 0; i < VQ_D; i++) {
            float v = sx[tid][i];
            s  = __fadd_rn(s, __fmul_rn(v, v));   // strict sequential ascending
            s1 += fabsf(v);
        }
        g_A[row0 + tid]  = s;
        g_S1[row0 + tid] = s1;
    }
}

// ---------------------------------------------------------------- prep c
__global__ __launch_bounds__(256) void vq_prep_c(const float* __restrict__ cb) {
    __shared__ float sc[32][257];
    __shared__ float smax[256];
    const int tid = threadIdx.x;
    const int row0 = blockIdx.x * 32;
    float m = 0.0f;
#pragma unroll
    for (int it = 0; it < 8; it++) {
        int idx = tid + it * 256;
        int r   = idx >> 6;
        int c4  = idx & 63;
        float4 v = ((const float4*)(cb + (size_t)(row0 + r) * VQ_D))[c4];
        sc[r][c4 * 4 + 0] = v.x; sc[r][c4 * 4 + 1] = v.y;
        sc[r][c4 * 4 + 2] = v.z; sc[r][c4 * 4 + 3] = v.w;
        m = fmaxf(m, fmaxf(fmaxf(fabsf(v.x), fabsf(v.y)), fmaxf(fabsf(v.z), fabsf(v.w))));
        __nv_bfloat162 p0, p1;
        p0.x = __float2bfloat16(v.x); p0.y = __float2bfloat16(v.y);
        p1.x = __float2bfloat16(v.z); p1.y = __float2bfloat16(v.w);
        __nv_bfloat162* dst = (__nv_bfloat162*)(g_ch + (size_t)(row0 + r) * VQ_D);
        dst[c4 * 2] = p0; dst[c4 * 2 + 1] = p1;
    }
    smax[tid] = m;
    __syncthreads();
    if (tid < 32) {
        float s = 0.0f;
        for (int i = 0; i < VQ_D; i++) {
            float v = sc[tid][i];
            s = __fadd_rn(s, __fmul_rn(v, v));    // strict sequential ascending
        }
        g_B[row0 + tid] = s;
    }
    for (int s = 128; s > 0; s >>= 1) {
        if (tid < s) smax[tid] = fmaxf(smax[tid], smax[tid + s]);
        __syncthreads();
    }
    if (tid == 0) atomicMax(&g_cmaxbits, __float_as_uint(smax[0]));
}

// ---------------------------------------------------------------- bf16 MMA gemm + candidate collect
__global__ __launch_bounds__(GT, 1) void vq_gemm_kernel() {
    extern __shared__ unsigned smem_dyn[];
    unsigned* xsw = smem_dyn;                    // GM x XW
    unsigned* csw = smem_dyn + GM * XW;          // 2 x (GN x XW)
    __shared__ unsigned s_rowmin[GM];

    const int tid  = threadIdx.x;
    const int w    = tid >> 5;                   // 0..15
    const int lane = tid & 31;
    const int g    = lane >> 2;
    const int tg   = lane & 3;
    const int rowbase = (w >> 1) * 32;           // 8 row-groups of 32
    const int colbase = (w & 1) * 32;            // 2 col-groups of 32
    const int row0 = blockIdx.x * GM;

    // ldmatrix per-lane addressing (group j = lane>>3, rl = lane&7):
    //   A.x4 regs: j0 rows+0..7 colw0 | j1 rows+8..15 colw0 | j2 rows+0..7 colw4 | j3 rows+8..15 colw4
    //   B.x4 regs: j0 n+0..7 colw0 (b0,nt p) | j1 n+0..7 colw4 (b1,nt p) | j2 n+8..15 colw0 | j3 colw4
    const int j  = lane >> 3;
    const int rl = lane & 7;
    const int a_row  = rowbase + (j & 1) * 8 + rl;
    const int a_colw = (j >> 1) * 4;
    const unsigned a_addr0 = smem_u32(xsw + a_row * XW + a_colw);
    const unsigned a_addr1 = smem_u32(xsw + (a_row + 16) * XW + a_colw);
    const int b_row  = colbase + (j >> 1) * 8 + rl;
    const int b_colw = (j & 1) * 4;
    const unsigned b_off01 = (unsigned)((b_row * XW + b_colw) * 4);        // nt 0,1
    const unsigned b_off23 = (unsigned)(((b_row + 16) * XW + b_colw) * 4); // nt 2,3

    // async-load x tile [GM x 256 bf16] and c tile 0
    for (int idx = tid; idx < GM * 32; idx += GT) {
        int r = idx >> 5, sl = idx & 31;
        cp16(smem_u32(xsw + r * XW + sl * 4),
             (const uint4*)(g_xh + (size_t)(row0 + r) * VQ_D) + sl);
    }
    for (int idx = tid; idx < GN * 32; idx += GT) {
        int r = idx >> 5, sl = idx & 31;
        cp16(smem_u32(csw + r * XW + sl * 4),
             (const uint4*)(g_ch + (size_t)r * VQ_D) + sl);
    }
    CP_COMMIT();
    if (tid < GM) s_rowmin[tid] = 0x7f7fffffu;   // FLT_MAX bits

    // per-thread rows: rowbase + (mi>>1)*16 + (mi&1)*8 + g
    int   lrow[4];
    float Arow[4], thr[4], runmin[4];
    float cmax = __uint_as_float(g_cmaxbits);
#pragma unroll
    for (int mi = 0; mi < 4; mi++) {
        int lr = rowbase + (mi >> 1) * 16 + (mi & 1) * 8 + g;
        lrow[mi]   = lr;
        Arow[mi]   = g_A[row0 + lr];
        thr[mi]    = 0.033f * cmax * g_S1[row0 + lr] + 4.0e-4f;  // certified 2*eps
        runmin[mi] = FLT_MAX;
    }

    CP_WAIT0();
    __syncthreads();

    for (int t = 0; t < NT; t++) {
        unsigned* cur = csw + (t & 1) * (GN * XW);
        const unsigned cbase = smem_u32(cur);
        if (t + 1 < NT) {
            unsigned* nxt = csw + ((t + 1) & 1) * (GN * XW);
            const __nv_bfloat16* src = g_ch + (size_t)(t + 1) * GN * VQ_D;
            for (int idx = tid; idx < GN * 32; idx += GT) {
                int r = idx >> 5, sl = idx & 31;
                cp16(smem_u32(nxt + r * XW + sl * 4),
                     (const uint4*)(src + (size_t)r * VQ_D) + sl);
            }
            CP_COMMIT();
        }

        float acc[2][4][4];
#pragma unroll
        for (int mt = 0; mt < 2; mt++)
#pragma unroll
            for (int nt = 0; nt < 4; nt++)
#pragma unroll
                for (int q = 0; q < 4; q++) acc[mt][nt][q] = 0.0f;

#pragma unroll
        for (int i = 0; i < 16; i++) {
            const unsigned step = (unsigned)(i * 32);   // 8 words = 32 bytes per k16
            unsigned a0[4], a1[4], b01[4], b23[4];
            ldsm4(a0[0], a0[1], a0[2], a0[3], a_addr0 + step);
            ldsm4(a1[0], a1[1], a1[2], a1[3], a_addr1 + step);
            ldsm4(b01[0], b01[1], b01[2], b01[3], cbase + b_off01 + step);
            ldsm4(b23[0], b23[1], b23[2], b23[3], cbase + b_off23 + step);
            mma16816(acc[0][0], a0[0], a0[1], a0[2], a0[3], b01[0], b01[1]);
            mma16816(acc[0][1], a0[0], a0[1], a0[2], a0[3], b01[2], b01[3]);
            mma16816(acc[0][2], a0[0], a0[1], a0[2], a0[3], b23[0], b23[1]);
            mma16816(acc[0][3], a0[0], a0[1], a0[2], a0[3], b23[2], b23[3]);
            mma16816(acc[1][0], a1[0], a1[1], a1[2], a1[3], b01[0], b01[1]);
            mma16816(acc[1][1], a1[0], a1[1], a1[2], a1[3], b01[2], b01[3]);
            mma16816(acc[1][2], a1[0], a1[1], a1[2], a1[3], b23[0], b23[1]);
            mma16816(acc[1][3], a1[0], a1[1], a1[2], a1[3], b23[2], b23[3]);
        }

        // epilogue: dist, quad-reduced local min, stale-shared-min threshold
        const int kb = t * GN + colbase;
        float lmin[4] = {FLT_MAX, FLT_MAX, FLT_MAX, FLT_MAX};
#pragma unroll
        for (int nt = 0; nt < 4; nt++) {
            float B0 = g_B[kb + nt * 8 + 2 * tg];
            float B1 = g_B[kb + nt * 8 + 2 * tg + 1];
#pragma unroll
            for (int mt = 0; mt < 2; mt++) {
                float d00 = (Arow[2 * mt] + B0)     - 2.0f * acc[mt][nt][0];
                float d01 = (Arow[2 * mt] + B1)     - 2.0f * acc[mt][nt][1];
                float d10 = (Arow[2 * mt + 1] + B0) - 2.0f * acc[mt][nt][2];
                float d11 = (Arow[2 * mt + 1] + B1) - 2.0f * acc[mt][nt][3];
                acc[mt][nt][0] = d00; acc[mt][nt][1] = d01;
                acc[mt][nt][2] = d10; acc[mt][nt][3] = d11;
                lmin[2 * mt]     = fminf(lmin[2 * mt],     fminf(d00, d01));
                lmin[2 * mt + 1] = fminf(lmin[2 * mt + 1], fminf(d10, d11));
            }
        }
#pragma unroll
        for (int mi = 0; mi < 4; mi++) {
            lmin[mi] = fminf(lmin[mi], __shfl_xor_sync(0xffffffffu, lmin[mi], 1));
            lmin[mi] = fminf(lmin[mi], __shfl_xor_sync(0xffffffffu, lmin[mi], 2));
        }
        float rm[4];
#pragma unroll
        for (int mi = 0; mi < 4; mi++) {
            runmin[mi] = fminf(runmin[mi], lmin[mi]);
            float shared_min = __uint_as_float(s_rowmin[lrow[mi]]);  // stale: prev tiles
            rm[mi] = fminf(shared_min, runmin[mi]) + thr[mi];
            if (tg == 0)
                atomicMin(&s_rowmin[lrow[mi]], __float_as_uint(runmin[mi]));
        }
#pragma unroll
        for (int nt = 0; nt < 4; nt++) {
            int kA = kb + nt * 8 + 2 * tg;
#pragma unroll
            for (int mt = 0; mt < 2; mt++) {
#pragma unroll
                for (int q = 0; q < 4; q++) {
                    int mi = 2 * mt + (q >> 1);
                    if (acc[mt][nt][q] < rm[mi]) {
                        int grow = row0 + lrow[mi];
                        int pos = atomicAdd(&g_candCnt[grow], 1);
                        if (pos < CAP) g_cand[grow * CAP + pos] = kA + (q & 1);
                    }
                }
            }
        }

        CP_WAIT0();
        __syncthreads();   // next buffer ready; all reads of cur done
    }
}

// ---------------------------------------------------------------- exact rescore (warp per row)
__device__ __forceinline__ float exact_dist(const float* __restrict__ xr,
                                            const float* __restrict__ ck,
                                            float Ar, float Bk) {
    float acc = 0.0f;
    const float4* x4 = (const float4*)xr;
    const float4* c4 = (const float4*)ck;
#pragma unroll 4
    for (int i = 0; i < VQ_D / 4; i++) {
        float4 a = __ldg(x4 + i);
        float4 b = __ldg(c4 + i);
        acc = __fmaf_rn(a.x, b.x, acc);
        acc = __fmaf_rn(a.y, b.y, acc);
        acc = __fmaf_rn(a.z, b.z, acc);
        acc = __fmaf_rn(a.w, b.w, acc);
    }
    float t  = __fadd_rn(Ar, Bk);
    float m2 = __fmul_rn(2.0f, acc);
    return __fsub_rn(t, m2);
}

__global__ void vq_rescore_kernel(const float* __restrict__ x,
                                  const float* __restrict__ cb) {
    int row  = blockIdx.x * 8 + (threadIdx.x >> 5);
    int lane = threadIdx.x & 31;
    if (row >= VQ_N) return;
    int cnt = g_candCnt[row];
    const float* xr = x + (size_t)row * VQ_D;
    float Ar = g_A[row];

    float best = FLT_MAX;
    int   besti = 0x7fffffff;
    if (cnt <= CAP) {
        for (int jc = lane; jc < cnt; jc += 32) {
            int k = g_cand[row * CAP + jc];
            float d = exact_dist(xr, cb + (size_t)k * VQ_D, Ar, g_B[k]);
            if (d < best || (d == best && k < besti)) { best = d; besti = k; }
        }
    } else {
        for (int k = lane; k < VQ_K; k += 32) {
            float d = exact_dist(xr, cb + (size_t)k * VQ_D, Ar, g_B[k]);
            if (d < best || (d == best && k < besti)) { best = d; besti = k; }
        }
    }
#pragma unroll
    for (int off = 16; off > 0; off >>= 1) {
        float v = __shfl_down_sync(0xffffffffu, best, off);
        int   i = __shfl_down_sync(0xffffffffu, besti, off);
        if (v < best || (v == best && i < besti)) { best = v; besti = i; }
    }
    if (lane == 0) g_ind[row] = besti;
}

// ---------------------------------------------------------------- output + loss accum
__global__ void vq_output_kernel(const float* __restrict__ x,
                                 const float* __restrict__ cb,
                                 float* __restrict__ out)
{
    __shared__ double sd[256];
    int e4 = blockIdx.x * blockDim.x + threadIdx.x;
    double ls = 0.0;
    if (e4 < VQ_N * VQ_D / 4) {
        int base = e4 * 4;
        int row  = base >> 8;
        int col  = base & 255;
        int ind  = g_ind[row];
        float4 xv = *(const float4*)(x  + base);
        float4 qv = *(const float4*)(cb + (size_t)ind * VQ_D + col);
        float d0 = __fsub_rn(qv.x, xv.x);
        float d1 = __fsub_rn(qv.y, xv.y);
        float d2 = __fsub_rn(qv.z, xv.z);
        float d3 = __fsub_rn(qv.w, xv.w);
        float4 ov;
        ov.x = __fadd_rn(xv.x, d0);
        ov.y = __fadd_rn(xv.y, d1);
        ov.z = __fadd_rn(xv.z, d2);
        ov.w = __fadd_rn(xv.w, d3);
        *(float4*)(out + base) = ov;
        ls = (double)__fmul_rn(d0, d0) + (double)__fmul_rn(d1, d1)
           + (double)__fmul_rn(d2, d2) + (double)__fmul_rn(d3, d3);
    }
    sd[threadIdx.x] = ls;
    __syncthreads();
    for (int s = 128; s > 0; s >>= 1) {
        if (threadIdx.x < s) sd[threadIdx.x] += sd[threadIdx.x + s];
        __syncthreads();
    }
    if (threadIdx.x == 0) atomicAdd(&g_losssum, sd[0]);
}

// ---------------------------------------------------------------- finalize loss
__global__ void vq_finalize_kernel(float* __restrict__ out, int has_loss) {
    if (!has_loss) return;
    float m = (float)(g_losssum * (1.0 / (double)(VQ_N * VQ_D)));
    float commit = __fmul_rn(m, 0.25f);
    out[VQ_N * VQ_D] = __fadd_rn(commit, m);
}

// ---------------------------------------------------------------- launch
extern "C" void kernel_launch(void* const* d_in, const int* in_sizes, int n_in,
                              void* d_out, int out_size)
{
    const float* latents  = (const float*)d_in[0];
    const float* codebook = (const float*)d_in[1];
    if (n_in >= 2 && in_sizes[0] == VQ_K * VQ_D && in_sizes[1] == VQ_N * VQ_D) {
        latents  = (const float*)d_in[1];
        codebook = (const float*)d_in[0];
    }
    float* out = (float*)d_out;
    int has_loss = (out_size > VQ_N * VQ_D) ? 1 : 0;

    const int GEMM_SMEM = (GM * XW + 2 * GN * XW) * 4;   // 202752 bytes
    cudaFuncSetAttribute(vq_gemm_kernel,
                         cudaFuncAttributeMaxDynamicSharedMemorySize, GEMM_SMEM);

    vq_zero_kernel<<<VQ_N / 256, 256>>>();
    vq_prep_c<<<VQ_K / 32, 256>>>(codebook);
    vq_prep_x<<<VQ_N / 32, 256>>>(latents);
    vq_gemm_kernel<<<VQ_N / GM, GT, GEMM_SMEM>>>();
    vq_rescore_kernel<<<VQ_N / 8, 256>>>(latents, codebook);
    vq_output_kernel<<<(VQ_N * VQ_D / 4) / 256, 256>>>(latents, codebook, out);
    vq_finalize_kernel<<<1, 1>>>(out, has_loss);
}

// round 9
// speedup vs baseline: 1.8114x; 1.2264x over previous
#include <cuda_runtime.h>
#include <cuda_bf16.h>
#include <math_constants.h>
#include <float.h>

// VectorQuantizer: N=32768 rows, D=256, K=4096.
// bf16 tensor-core filter (certified margin) + exact fp32 rescore.
// Exact chain (verified rel_err=0.0 R1-R7):
//   dist = fl( fl(A_r + B_k) - fl(2 * dot_seq_fma(x_r,c_k)) ), argmin lowest
//   index on ties.
// R9 (= R8 resubmit + ballot-guarded append): no __syncthreads in the k-loop.
// 3-buffer mbarrier ring for c tiles (full: cp.async.mbarrier.arrive.noinc
// x512; empty: per-thread arrive x512), produce-ahead 1 -> 2-tile warp skew
// slack. Unpadded smem rows (512B) with XOR-16B swizzle (chunk ^ (row&7)).

#define VQ_N 32768
#define VQ_D 256
#define VQ_K 4096

#define GM   256  // rows per CTA
#define GN   64   // codewords per tile
#define NT   (VQ_K / GN)
#define NBUF 3
#define CAP  256
#define GT   512
#define XWB  512  // bytes per smem row (256 bf16, unpadded)
#define CBUF (GN * XWB)            // 32768 B per c buffer
#define XBYTES (GM * XWB)          // 131072 B x tile

__device__ __nv_bfloat16 g_xh[VQ_N * VQ_D];
__device__ __nv_bfloat16 g_ch[VQ_K * VQ_D];
__device__ float    g_A[VQ_N];
__device__ float    g_S1[VQ_N];
__device__ float    g_B[VQ_K];
__device__ unsigned g_cmaxbits;
__device__ int      g_candCnt[VQ_N];
__device__ int      g_cand[VQ_N * CAP];
__device__ int      g_ind[VQ_N];
__device__ double   g_losssum;

// ---------------------------------------------------------------- helpers
__device__ __forceinline__ unsigned smem_u32(const void* p) {
    return (unsigned)__cvta_generic_to_shared(p);
}
__device__ __forceinline__ void cp16(unsigned dst, const void* src) {
    asm volatile("cp.async.cg.shared.global [%0], [%1], 16;\n" :: "r"(dst), "l"(src));
}
#define CP_COMMIT() asm volatile("cp.async.commit_group;\n")
#define CP_WAIT0()  asm volatile("cp.async.wait_group 0;\n")

__device__ __forceinline__ void mbar_init(unsigned addr, unsigned cnt) {
    asm volatile("mbarrier.init.shared.b64 [%0], %1;\n" :: "r"(addr), "r"(cnt) : "memory");
}
__device__ __forceinline__ void mbar_arrive(unsigned addr) {
    asm volatile("mbarrier.arrive.shared.b64 _, [%0];\n" :: "r"(addr) : "memory");
}
__device__ __forceinline__ void cpasync_arrive_noinc(unsigned addr) {
    asm volatile("cp.async.mbarrier.arrive.noinc.shared.b64 [%0];\n" :: "r"(addr) : "memory");
}
__device__ __forceinline__ void mbar_wait(unsigned addr, unsigned parity) {
    asm volatile(
        "{\n\t.reg .pred P;\n\t"
        "WAIT_%=:\n\t"
        "mbarrier.try_wait.parity.acquire.cta.shared::cta.b64 P, [%0], %1, 0x989680;\n\t"
        "@P bra.uni DONE_%=;\n\t"
        "bra.uni WAIT_%=;\n\t"
        "DONE_%=:\n\t}"
        :: "r"(addr), "r"(parity) : "memory");
}

__device__ __forceinline__ void ldsm4(unsigned& r0, unsigned& r1,
                                      unsigned& r2, unsigned& r3, unsigned addr) {
    asm volatile("ldmatrix.sync.aligned.m8n8.x4.shared.b16 {%0,%1,%2,%3}, [%4];\n"
                 : "=r"(r0), "=r"(r1), "=r"(r2), "=r"(r3) : "r"(addr));
}
__device__ __forceinline__ void mma16816(float c[4], unsigned a0, unsigned a1,
                                         unsigned a2, unsigned a3,
                                         unsigned b0, unsigned b1) {
    asm volatile(
        "mma.sync.aligned.m16n8k16.row.col.f32.bf16.bf16.f32 "
        "{%0,%1,%2,%3}, {%4,%5,%6,%7}, {%8,%9}, {%0,%1,%2,%3};\n"
        : "+f"(c[0]), "+f"(c[1]), "+f"(c[2]), "+f"(c[3])
        : "r"(a0), "r"(a1), "r"(a2), "r"(a3), "r"(b0), "r"(b1));
}

// ---------------------------------------------------------------- zero
__global__ void vq_zero_kernel() {
    int i = blockIdx.x * blockDim.x + threadIdx.x;
    if (i < VQ_N) g_candCnt[i] = 0;
    if (i == 0) { g_losssum = 0.0; g_cmaxbits = 0u; }
}

// ---------------------------------------------------------------- prep x
__global__ __launch_bounds__(256) void vq_prep_x(const float* __restrict__ x) {
    __shared__ float sx[32][257];
    const int tid = threadIdx.x;
    const int row0 = blockIdx.x * 32;
#pragma unroll
    for (int it = 0; it < 8; it++) {
        int idx = tid + it * 256;
        int r   = idx >> 6;
        int c4  = idx & 63;
        float4 v = ((const float4*)(x + (size_t)(row0 + r) * VQ_D))[c4];
        sx[r][c4 * 4 + 0] = v.x; sx[r][c4 * 4 + 1] = v.y;
        sx[r][c4 * 4 + 2] = v.z; sx[r][c4 * 4 + 3] = v.w;
        __nv_bfloat162 p0, p1;
        p0.x = __float2bfloat16(v.x); p0.y = __float2bfloat16(v.y);
        p1.x = __float2bfloat16(v.z); p1.y = __float2bfloat16(v.w);
        __nv_bfloat162* dst = (__nv_bfloat162*)(g_xh + (size_t)(row0 + r) * VQ_D);
        dst[c4 * 2] = p0; dst[c4 * 2 + 1] = p1;
    }
    __syncthreads();
    if (tid < 32) {
        float s = 0.0f, s1 = 0.0f;
        for (int i = 0; i < VQ_D; i++) {
            float v = sx[tid][i];
            s  = __fadd_rn(s, __fmul_rn(v, v));   // strict sequential ascending
            s1 += fabsf(v);
        }
        g_A[row0 + tid]  = s;
        g_S1[row0 + tid] = s1;
    }
}

// ---------------------------------------------------------------- prep c
__global__ __launch_bounds__(256) void vq_prep_c(const float* __restrict__ cb) {
    __shared__ float sc[32][257];
    __shared__ float smax[256];
    const int tid = threadIdx.x;
    const int row0 = blockIdx.x * 32;
    float m = 0.0f;
#pragma unroll
    for (int it = 0; it < 8; it++) {
        int idx = tid + it * 256;
        int r   = idx >> 6;
        int c4  = idx & 63;
        float4 v = ((const float4*)(cb + (size_t)(row0 + r) * VQ_D))[c4];
        sc[r][c4 * 4 + 0] = v.x; sc[r][c4 * 4 + 1] = v.y;
        sc[r][c4 * 4 + 2] = v.z; sc[r][c4 * 4 + 3] = v.w;
        m = fmaxf(m, fmaxf(fmaxf(fabsf(v.x), fabsf(v.y)), fmaxf(fabsf(v.z), fabsf(v.w))));
        __nv_bfloat162 p0, p1;
        p0.x = __float2bfloat16(v.x); p0.y = __float2bfloat16(v.y);
        p1.x = __float2bfloat16(v.z); p1.y = __float2bfloat16(v.w);
        __nv_bfloat162* dst = (__nv_bfloat162*)(g_ch + (size_t)(row0 + r) * VQ_D);
        dst[c4 * 2] = p0; dst[c4 * 2 + 1] = p1;
    }
    smax[tid] = m;
    __syncthreads();
    if (tid < 32) {
        float s = 0.0f;
        for (int i = 0; i < VQ_D; i++) {
            float v = sc[tid][i];
            s = __fadd_rn(s, __fmul_rn(v, v));    // strict sequential ascending
        }
        g_B[row0 + tid] = s;
    }
    for (int s = 128; s > 0; s >>= 1) {
        if (tid < s) smax[tid] = fmaxf(smax[tid], smax[tid + s]);
        __syncthreads();
    }
    if (tid == 0) atomicMax(&g_cmaxbits, __float_as_uint(smax[0]));
}

// ---------------------------------------------------------------- gemm + candidate collect
__global__ __launch_bounds__(GT, 1) void vq_gemm_kernel() {
    extern __shared__ unsigned char smem_dyn[];
    unsigned char* xs = smem_dyn;              // XBYTES
    unsigned char* cs = smem_dyn + XBYTES;     // NBUF * CBUF
    __shared__ unsigned long long s_full[NBUF], s_empty[NBUF];
    __shared__ unsigned s_rowmin[GM];

    const int tid  = threadIdx.x;
    const int w    = tid >> 5;
    const int lane = tid & 31;
    const int g    = lane >> 2;
    const int tg   = lane & 3;
    const int rowbase = (w >> 1) * 32;
    const int colbase = (w & 1) * 32;
    const int row0 = blockIdx.x * GM;
    const unsigned xs_b = smem_u32(xs);
    const unsigned cs_b = smem_u32(cs);

    // ldmatrix lane addressing (same logical layout as R7, swizzled rows)
    const int j  = lane >> 3;
    const int rl = lane & 7;
    const int a_row  = rowbase + (j & 1) * 8 + rl;     // a_row+16 same &7
    const unsigned sA = (unsigned)(a_row & 7);
    const unsigned cA = (unsigned)(j >> 1);
    const unsigned xA0 = xs_b + a_row * XWB;
    const unsigned xA1 = xA0 + 16 * XWB;
    const int b_row  = colbase + (j >> 1) * 8 + rl;
    const unsigned sB = (unsigned)(b_row & 7);
    const unsigned cB = (unsigned)(j & 1);
    const unsigned bo0 = (unsigned)(b_row * XWB);
    const unsigned bo1 = bo0 + 16 * XWB;

    // async-copy x tile, swizzled: chunk c (16B) of row r -> (c ^ (r&7))
#pragma unroll
    for (int q = 0; q < 16; q++) {
        int idx = tid + q * GT;
        int r = idx >> 5, c = idx & 31;
        cp16(xs_b + r * XWB + (unsigned)((c ^ (r & 7)) << 4),
             (const uint4*)(g_xh + (size_t)(row0 + r) * VQ_D) + c);
    }
    CP_COMMIT();

    if (tid < GM) s_rowmin[tid] = 0x7f7fffffu;
    if (tid == 0) {
#pragma unroll
        for (int s = 0; s < NBUF; s++) {
            mbar_init(smem_u32(&s_full[s]), GT);
            mbar_init(smem_u32(&s_empty[s]), GT);
        }
    }

    int   lrow[4];
    float Arow[4], thr[4], runmin[4];
    float cmax = __uint_as_float(g_cmaxbits);
#pragma unroll
    for (int mi = 0; mi < 4; mi++) {
        int lr = rowbase + (mi >> 1) * 16 + (mi & 1) * 8 + g;
        lrow[mi]   = lr;
        Arow[mi]   = g_A[row0 + lr];
        thr[mi]    = 0.033f * cmax * g_S1[row0 + lr] + 4.0e-4f;  // certified 2*eps
        runmin[mi] = FLT_MAX;
    }

    CP_WAIT0();
    __syncthreads();   // x in smem, barriers initialized, rowmin visible

    // produce tile 0 (cycle 0, no empty wait)
    {
        const __nv_bfloat16* src = g_ch;
#pragma unroll
        for (int q = 0; q < 4; q++) {
            int idx = tid + q * GT;
            int r = idx >> 5, c = idx & 31;
            cp16(cs_b + r * XWB + (unsigned)((c ^ (r & 7)) << 4),
                 (const uint4*)(src + (size_t)r * VQ_D) + c);
        }
        cpasync_arrive_noinc(smem_u32(&s_full[0]));
    }

    for (int t = 0; t < NT; t++) {
        // produce tile t+1 before consuming t (overlap copy with MMA)
        int u = t + 1;
        if (u < NT) {
            int bu = u % NBUF;
            if (u >= NBUF)
                mbar_wait(smem_u32(&s_empty[bu]), (unsigned)((u / NBUF - 1) & 1));
            const __nv_bfloat16* src = g_ch + (size_t)u * GN * VQ_D;
            unsigned base = cs_b + bu * CBUF;
#pragma unroll
            for (int q = 0; q < 4; q++) {
                int idx = tid + q * GT;
                int r = idx >> 5, c = idx & 31;
                cp16(base + r * XWB + (unsigned)((c ^ (r & 7)) << 4),
                     (const uint4*)(src + (size_t)r * VQ_D) + c);
            }
            cpasync_arrive_noinc(smem_u32(&s_full[bu]));
        }

        const int b = t % NBUF;
        mbar_wait(smem_u32(&s_full[b]), (unsigned)((t / NBUF) & 1));
        const unsigned cur = cs_b + b * CBUF;

        float acc[2][4][4];
#pragma unroll
        for (int mt = 0; mt < 2; mt++)
#pragma unroll
            for (int nt = 0; nt < 4; nt++)
#pragma unroll
                for (int q = 0; q < 4; q++) acc[mt][nt][q] = 0.0f;

#pragma unroll
        for (int i = 0; i < 16; i++) {
            unsigned tA = (((unsigned)(2 * i) + cA) ^ sA) << 4;
            unsigned tB = (((unsigned)(2 * i) + cB) ^ sB) << 4;
            unsigned a0[4], a1[4], b01[4], b23[4];
            ldsm4(a0[0], a0[1], a0[2], a0[3], xA0 + tA);
            ldsm4(a1[0], a1[1], a1[2], a1[3], xA1 + tA);
            ldsm4(b01[0], b01[1], b01[2], b01[3], cur + bo0 + tB);
            ldsm4(b23[0], b23[1], b23[2], b23[3], cur + bo1 + tB);
            mma16816(acc[0][0], a0[0], a0[1], a0[2], a0[3], b01[0], b01[1]);
            mma16816(acc[0][1], a0[0], a0[1], a0[2], a0[3], b01[2], b01[3]);
            mma16816(acc[0][2], a0[0], a0[1], a0[2], a0[3], b23[0], b23[1]);
            mma16816(acc[0][3], a0[0], a0[1], a0[2], a0[3], b23[2], b23[3]);
            mma16816(acc[1][0], a1[0], a1[1], a1[2], a1[3], b01[0], b01[1]);
            mma16816(acc[1][1], a1[0], a1[1], a1[2], a1[3], b01[2], b01[3]);
            mma16816(acc[1][2], a1[0], a1[1], a1[2], a1[3], b23[0], b23[1]);
            mma16816(acc[1][3], a1[0], a1[1], a1[2], a1[3], b23[2], b23[3]);
        }

        // epilogue: dist, quad-reduced local min, stale-shared-min threshold
        const int kb = t * GN + colbase;
        float lmin[4] = {FLT_MAX, FLT_MAX, FLT_MAX, FLT_MAX};
#pragma unroll
        for (int nt = 0; nt < 4; nt++) {
            float B0 = g_B[kb + nt * 8 + 2 * tg];
            float B1 = g_B[kb + nt * 8 + 2 * tg + 1];
#pragma unroll
            for (int mt = 0; mt < 2; mt++) {
                float d00 = (Arow[2 * mt] + B0)     - 2.0f * acc[mt][nt][0];
                float d01 = (Arow[2 * mt] + B1)     - 2.0f * acc[mt][nt][1];
                float d10 = (Arow[2 * mt + 1] + B0) - 2.0f * acc[mt][nt][2];
                float d11 = (Arow[2 * mt + 1] + B1) - 2.0f * acc[mt][nt][3];
                acc[mt][nt][0] = d00; acc[mt][nt][1] = d01;
                acc[mt][nt][2] = d10; acc[mt][nt][3] = d11;
                lmin[2 * mt]     = fminf(lmin[2 * mt],     fminf(d00, d01));
                lmin[2 * mt + 1] = fminf(lmin[2 * mt + 1], fminf(d10, d11));
            }
        }
#pragma unroll
        for (int mi = 0; mi < 4; mi++) {
            lmin[mi] = fminf(lmin[mi], __shfl_xor_sync(0xffffffffu, lmin[mi], 1));
            lmin[mi] = fminf(lmin[mi], __shfl_xor_sync(0xffffffffu, lmin[mi], 2));
        }
        float rm[4];
        bool mine = false;
#pragma unroll
        for (int mi = 0; mi < 4; mi++) {
            runmin[mi] = fminf(runmin[mi], lmin[mi]);
            float shared_min = __uint_as_float(s_rowmin[lrow[mi]]);  // stale ok
            rm[mi] = fminf(shared_min, runmin[mi]) + thr[mi];
            if (tg == 0)
                atomicMin(&s_rowmin[lrow[mi]], __float_as_uint(runmin[mi]));
        }
#pragma unroll
        for (int nt = 0; nt < 4; nt++)
#pragma unroll
            for (int mt = 0; mt < 2; mt++)
#pragma unroll
                for (int q = 0; q < 4; q++)
                    mine |= (acc[mt][nt][q] < rm[2 * mt + (q >> 1)]);

        // ballot-guard: skip branchy append loop when no lane has a candidate
        if (__ballot_sync(0xffffffffu, mine)) {
#pragma unroll
            for (int nt = 0; nt < 4; nt++) {
                int kA = kb + nt * 8 + 2 * tg;
#pragma unroll
                for (int mt = 0; mt < 2; mt++) {
#pragma unroll
                    for (int q = 0; q < 4; q++) {
                        int mi = 2 * mt + (q >> 1);
                        if (acc[mt][nt][q] < rm[mi]) {
                            int grow = row0 + lrow[mi];
                            int pos = atomicAdd(&g_candCnt[grow], 1);
                            if (pos < CAP) g_cand[grow * CAP + pos] = kA + (q & 1);
                        }
                    }
                }
            }
        }

        mbar_arrive(smem_u32(&s_empty[b]));   // done reading buffer b
    }
}

// ---------------------------------------------------------------- exact rescore
__device__ __forceinline__ float exact_dist(const float* __restrict__ xr,
                                            const float* __restrict__ ck,
                                            float Ar, float Bk) {
    float acc = 0.0f;
    const float4* x4 = (const float4*)xr;
    const float4* c4 = (const float4*)ck;
#pragma unroll 4
    for (int i = 0; i < VQ_D / 4; i++) {
        float4 a = __ldg(x4 + i);
        float4 b = __ldg(c4 + i);
        acc = __fmaf_rn(a.x, b.x, acc);
        acc = __fmaf_rn(a.y, b.y, acc);
        acc = __fmaf_rn(a.z, b.z, acc);
        acc = __fmaf_rn(a.w, b.w, acc);
    }
    float t  = __fadd_rn(Ar, Bk);
    float m2 = __fmul_rn(2.0f, acc);
    return __fsub_rn(t, m2);
}

__global__ void vq_rescore_kernel(const float* __restrict__ x,
                                  const float* __restrict__ cb) {
    int row  = blockIdx.x * 8 + (threadIdx.x >> 5);
    int lane = threadIdx.x & 31;
    if (row >= VQ_N) return;
    int cnt = g_candCnt[row];
    const float* xr = x + (size_t)row * VQ_D;
    float Ar = g_A[row];

    float best = FLT_MAX;
    int   besti = 0x7fffffff;
    if (cnt <= CAP) {
        for (int jc = lane; jc < cnt; jc += 32) {
            int k = g_cand[row * CAP + jc];
            float d = exact_dist(xr, cb + (size_t)k * VQ_D, Ar, g_B[k]);
            if (d < best || (d == best && k < besti)) { best = d; besti = k; }
        }
    } else {
        for (int k = lane; k < VQ_K; k += 32) {
            float d = exact_dist(xr, cb + (size_t)k * VQ_D, Ar, g_B[k]);
            if (d < best || (d == best && k < besti)) { best = d; besti = k; }
        }
    }
#pragma unroll
    for (int off = 16; off > 0; off >>= 1) {
        float v = __shfl_down_sync(0xffffffffu, best, off);
        int   i = __shfl_down_sync(0xffffffffu, besti, off);
        if (v < best || (v == best && i < besti)) { best = v; besti = i; }
    }
    if (lane == 0) g_ind[row] = besti;
}

// ---------------------------------------------------------------- output + loss
__global__ void vq_output_kernel(const float* __restrict__ x,
                                 const float* __restrict__ cb,
                                 float* __restrict__ out)
{
    __shared__ double sd[256];
    int e4 = blockIdx.x * blockDim.x + threadIdx.x;
    double ls = 0.0;
    if (e4 < VQ_N * VQ_D / 4) {
        int base = e4 * 4;
        int row  = base >> 8;
        int col  = base & 255;
        int ind  = g_ind[row];
        float4 xv = *(const float4*)(x  + base);
        float4 qv = *(const float4*)(cb + (size_t)ind * VQ_D + col);
        float d0 = __fsub_rn(qv.x, xv.x);
        float d1 = __fsub_rn(qv.y, xv.y);
        float d2 = __fsub_rn(qv.z, xv.z);
        float d3 = __fsub_rn(qv.w, xv.w);
        float4 ov;
        ov.x = __fadd_rn(xv.x, d0);
        ov.y = __fadd_rn(xv.y, d1);
        ov.z = __fadd_rn(xv.z, d2);
        ov.w = __fadd_rn(xv.w, d3);
        *(float4*)(out + base) = ov;
        ls = (double)__fmul_rn(d0, d0) + (double)__fmul_rn(d1, d1)
           + (double)__fmul_rn(d2, d2) + (double)__fmul_rn(d3, d3);
    }
    sd[threadIdx.x] = ls;
    __syncthreads();
    for (int s = 128; s > 0; s >>= 1) {
        if (threadIdx.x < s) sd[threadIdx.x] += sd[threadIdx.x + s];
        __syncthreads();
    }
    if (threadIdx.x == 0) atomicAdd(&g_losssum, sd[0]);
}

// ---------------------------------------------------------------- finalize loss
__global__ void vq_finalize_kernel(float* __restrict__ out, int has_loss) {
    if (!has_loss) return;
    float m = (float)(g_losssum * (1.0 / (double)(VQ_N * VQ_D)));
    float commit = __fmul_rn(m, 0.25f);
    out[VQ_N * VQ_D] = __fadd_rn(commit, m);
}

// ---------------------------------------------------------------- launch
extern "C" void kernel_launch(void* const* d_in, const int* in_sizes, int n_in,
                              void* d_out, int out_size)
{
    const float* latents  = (const float*)d_in[0];
    const float* codebook = (const float*)d_in[1];
    if (n_in >= 2 && in_sizes[0] == VQ_K * VQ_D && in_sizes[1] == VQ_N * VQ_D) {
        latents  = (const float*)d_in[1];
        codebook = (const float*)d_in[0];
    }
    float* out = (float*)d_out;
    int has_loss = (out_size > VQ_N * VQ_D) ? 1 : 0;

    const int GEMM_SMEM = XBYTES + NBUF * CBUF;   // 229376 bytes
    cudaFuncSetAttribute(vq_gemm_kernel,
                         cudaFuncAttributeMaxDynamicSharedMemorySize, GEMM_SMEM);

    vq_zero_kernel<<<VQ_N / 256, 256>>>();
    vq_prep_c<<<VQ_K / 32, 256>>>(codebook);
    vq_prep_x<<<VQ_N / 32, 256>>>(latents);
    vq_gemm_kernel<<<VQ_N / GM, GT, GEMM_SMEM>>>();
    vq_rescore_kernel<<<VQ_N / 8, 256>>>(latents, codebook);
    vq_output_kernel<<<(VQ_N * VQ_D / 4) / 256, 256>>>(latents, codebook, out);
    vq_finalize_kernel<<<1, 1>>>(out, has_loss);
}